// round 1
// baseline (speedup 1.0000x reference)
#include <cuda_runtime.h>
#include <math.h>

// ---------------------------------------------------------------------------
// Problem constants
// ---------------------------------------------------------------------------
#define MTOT 8192      // tokens (B)
#define NTOT 256       // experts (E)
#define KTOT 7168      // hidden (H)

#define BM 128
#define BN 128
#define BK 16
#define NKT (KTOT / BK)   // 448

#define SA2 260        // floats per k-row of duplicated A (2*128 + 4 pad -> 2-way max store conflict)

#define N_GROUP 8
#define GROUP_SIZE 32
#define TOPK 8

typedef unsigned long long ull;

// Scratch for logits (8192*256 fp32 = 8 MB). Static device array: allowed.
__device__ float g_logits[(size_t)MTOT * NTOT];

// ---------------------------------------------------------------------------
// f32x2 packed FMA (Blackwell sm_10x; ptxas never emits FFMA2 from C++)
// ---------------------------------------------------------------------------
__device__ __forceinline__ ull ffma2(ull a, ull b, ull c) {
    ull d;
    asm("fma.rn.f32x2 %0, %1, %2, %3;" : "=l"(d) : "l"(a), "l"(b), "l"(c));
    return d;
}

__device__ __forceinline__ ull dup2(float x) {
    ull d;
    unsigned int xi = __float_as_uint(x);
    asm("mov.b64 %0, {%1, %1};" : "=l"(d) : "r"(xi));
    return d;
}

// ---------------------------------------------------------------------------
// GEMM: logits[M,N] = x[M,K] @ W[K,N], fp32, FFMA2 microkernel
// grid (NTOT/BN, MTOT/BM) = (2, 64); 256 threads
// ---------------------------------------------------------------------------
__global__ __launch_bounds__(256, 1)
void gemm_kernel(const float* __restrict__ A, const float* __restrict__ B) {
    __shared__ float sA[BK * SA2];   // duplicated A: row k holds [a0,a0,a1,a1,...]
    __shared__ float sB[BK * BN];    // natural B tile: row k holds 128 cols

    const int tid = threadIdx.x;
    const int tx = tid & 15;         // 0..15 (n direction)
    const int ty = tid >> 4;         // 0..15 (m direction)
    const int bm = blockIdx.y * BM;
    const int bn = blockIdx.x * BN;

    // --- global load mapping ---
    // A tile: 128 rows x 16 k = 512 float4 (4 float4 per row). float4 f: m=f>>2, kg=f&3.
    const int mA0 = tid >> 2;        // 0..63 (second chunk: +64)
    const int kg0 = tid & 3;
    const float* gA  = A + (size_t)(bm + mA0) * KTOT + kg0 * 4;
    const float* gA2 = gA + (size_t)64 * KTOT;

    // B tile: 16 rows x 128 cols = 512 float4 (32 per row). f: kr=f>>5, nc=(f&31)*4.
    const int kr0 = tid >> 5;        // 0..7 (second chunk: +8)
    const int nc0 = (tid & 31) * 4;
    const float* gB  = B + (size_t)kr0 * NTOT + bn + nc0;
    const float* gB2 = gB + (size_t)8 * NTOT;

    float4 ra0, ra1, rb0, rb1;

    ull acc[8][4];
#pragma unroll
    for (int i = 0; i < 8; i++)
#pragma unroll
        for (int j = 0; j < 4; j++) acc[i][j] = 0ULL;

    auto store_tiles = [&]() {
#pragma unroll
        for (int j = 0; j < 4; j++) {
            float* rowj = sA + (kg0 * 4 + j) * SA2;
            ((ull*)rowj)[mA0]      = dup2(((const float*)&ra0)[j]);
            ((ull*)rowj)[mA0 + 64] = dup2(((const float*)&ra1)[j]);
        }
        *(float4*)(sB + kr0 * BN + nc0)       = rb0;
        *(float4*)(sB + (kr0 + 8) * BN + nc0) = rb1;
    };

    // preload tile 0
    ra0 = *(const float4*)(gA);
    ra1 = *(const float4*)(gA2);
    rb0 = *(const float4*)(gB);
    rb1 = *(const float4*)(gB2);
    store_tiles();
    __syncthreads();

    for (int kt = 0; kt < NKT; ++kt) {
        // prefetch next tile into registers (hidden under compute)
        if (kt + 1 < NKT) {
            const float* pA = gA + (size_t)(kt + 1) * BK;
            const float* pB = gB + (size_t)(kt + 1) * BK * NTOT;
            ra0 = *(const float4*)(pA);
            ra1 = *(const float4*)(pA + (size_t)64 * KTOT);
            rb0 = *(const float4*)(pB);
            rb1 = *(const float4*)(pB + (size_t)8 * NTOT);
        }

        // compute 16 k-steps
#pragma unroll
        for (int k = 0; k < BK; k++) {
            const float* rowA = sA + k * SA2;
            const float* rowB = sB + k * BN;
            // a pairs: duplicated, so each 16B load = 2 broadcast pairs
            ulonglong2 A0 = *(const ulonglong2*)(rowA + 8 * ty);            // rows 4ty, 4ty+1
            ulonglong2 A1 = *(const ulonglong2*)(rowA + 8 * ty + 4);        // rows 4ty+2, 4ty+3
            ulonglong2 A2 = *(const ulonglong2*)(rowA + 128 + 8 * ty);      // rows 64+4ty, +1
            ulonglong2 A3 = *(const ulonglong2*)(rowA + 128 + 8 * ty + 4);  // rows 64+4ty+2, +3
            ulonglong2 B0 = *(const ulonglong2*)(rowB + 4 * tx);            // cols 4tx..4tx+3
            ulonglong2 B1 = *(const ulonglong2*)(rowB + 64 + 4 * tx);       // cols 64+4tx..+3

            ull a2[8] = {A0.x, A0.y, A1.x, A1.y, A2.x, A2.y, A3.x, A3.y};
            ull b2[4] = {B0.x, B0.y, B1.x, B1.y};
#pragma unroll
            for (int i = 0; i < 8; i++)
#pragma unroll
                for (int j = 0; j < 4; j++) acc[i][j] = ffma2(a2[i], b2[j], acc[i][j]);
        }
        __syncthreads();
        if (kt + 1 < NKT) {
            store_tiles();
            __syncthreads();
        }
    }

    // epilogue: write packed pairs straight to logits scratch
#pragma unroll
    for (int i = 0; i < 8; i++) {
        int row = bm + ((i < 4) ? (4 * ty + i) : (64 + 4 * ty + (i - 4)));
        ull* orow = (ull*)(g_logits + (size_t)row * NTOT + bn);
        orow[2 * tx]          = acc[i][0];
        orow[2 * tx + 1]      = acc[i][1];
        orow[32 + 2 * tx]     = acc[i][2];
        orow[32 + 2 * tx + 1] = acc[i][3];
    }
}

// ---------------------------------------------------------------------------
// Routing: softmax + bias + group top2 -> top4 groups -> top8 experts -> weights
// one block per token, 256 threads (thread e = expert e, warp w = group w)
// ---------------------------------------------------------------------------
__global__ __launch_bounds__(256)
void routing_kernel(const float* __restrict__ bias, float* __restrict__ out, int out_size) {
    const int b = blockIdx.x;
    const int e = threadIdx.x;         // expert index 0..255
    const int w = e >> 5;              // group index 0..7
    const int lane = e & 31;

    __shared__ float sc[256];          // softmax scores
    __shared__ float mval[256];        // masked biased scores (mutated by top-8 loop)
    __shared__ float redmax[8], redsum[8];
    __shared__ float gsc[8];
    __shared__ int   gsel[8];
    __shared__ float rv[8];
    __shared__ int   ri[8];
    __shared__ int   chosen[8];

    float l = g_logits[(size_t)b * NTOT + e];

    // --- softmax max ---
    float m = l;
#pragma unroll
    for (int o = 16; o; o >>= 1) m = fmaxf(m, __shfl_xor_sync(0xFFFFFFFFu, m, o));
    if (lane == 0) redmax[w] = m;
    __syncthreads();
    if (e == 0) {
        float mm = redmax[0];
#pragma unroll
        for (int i = 1; i < 8; i++) mm = fmaxf(mm, redmax[i]);
        redmax[0] = mm;
    }
    __syncthreads();
    const float gmax = redmax[0];

    // --- softmax sum ---
    float p = expf(l - gmax);
    float s = p;
#pragma unroll
    for (int o = 16; o; o >>= 1) s += __shfl_xor_sync(0xFFFFFFFFu, s, o);
    if (lane == 0) redsum[w] = s;
    __syncthreads();
    if (e == 0) {
        float ss = redsum[0];
#pragma unroll
        for (int i = 1; i < 8; i++) ss += redsum[i];
        redsum[0] = ss;
    }
    __syncthreads();

    const float score = p / redsum[0];
    sc[e] = score;
    const float vb = score + bias[e];   // biased score

    // --- per-group top2 (warp butterfly, merging top-2 sets) ---
    float m1 = vb, m2 = -INFINITY;
#pragma unroll
    for (int o = 16; o; o >>= 1) {
        float o1 = __shfl_xor_sync(0xFFFFFFFFu, m1, o);
        float o2 = __shfl_xor_sync(0xFFFFFFFFu, m2, o);
        float r1 = fmaxf(m1, o1);
        float r2 = fmaxf(fminf(m1, o1), fmaxf(m2, o2));
        m1 = r1; m2 = r2;
    }
    if (lane == 0) gsc[w] = m1 + m2;
    __syncthreads();

    // --- top-4 groups (serial on thread 0; ties -> lower index, like lax.top_k) ---
    if (e == 0) {
#pragma unroll
        for (int i = 0; i < 8; i++) gsel[i] = 0;
        for (int t = 0; t < 4; t++) {
            float bv = -INFINITY; int bi = -1;
#pragma unroll
            for (int i = 0; i < 8; i++) {
                if (!gsel[i] && gsc[i] > bv) { bv = gsc[i]; bi = i; }
            }
            gsel[bi] = 1;
        }
    }
    __syncthreads();

    // masked biased score (reference: vb * -inf for dropped groups; vb > 0 always)
    mval[e] = gsel[w] ? vb : -INFINITY;
    __syncthreads();

    // --- top-8 experts: iterative argmax, ties -> lower index ---
    for (int r = 0; r < TOPK; r++) {
        float v = mval[e];
        int idx = e;
#pragma unroll
        for (int o = 16; o; o >>= 1) {
            float ov = __shfl_xor_sync(0xFFFFFFFFu, v, o);
            int   oi = __shfl_xor_sync(0xFFFFFFFFu, idx, o);
            if (ov > v || (ov == v && oi < idx)) { v = ov; idx = oi; }
        }
        if (lane == 0) { rv[w] = v; ri[w] = idx; }
        __syncthreads();
        if (e == 0) {
            float bv = rv[0]; int bi = ri[0];
#pragma unroll
            for (int i = 1; i < 8; i++) {
                if (rv[i] > bv || (rv[i] == bv && ri[i] < bi)) { bv = rv[i]; bi = ri[i]; }
            }
            chosen[r] = bi;
            mval[bi] = -INFINITY;
        }
        __syncthreads();
    }

    // --- weights: gather UNBIASED scores, normalize, eps + scale ---
    if (e == 0) {
        float wv[TOPK];
        float ssum = 0.0f;
#pragma unroll
        for (int r = 0; r < TOPK; r++) { wv[r] = sc[chosen[r]]; ssum += wv[r]; }
#pragma unroll
        for (int r = 0; r < TOPK; r++) {
            out[(size_t)b * TOPK + r] = (wv[r] / ssum + 1e-20f) * 2.5f;
        }
        if (out_size >= 2 * MTOT * TOPK) {
            float* oidx = out + (size_t)MTOT * TOPK;
#pragma unroll
            for (int r = 0; r < TOPK; r++) {
                oidx[(size_t)b * TOPK + r] = (float)chosen[r];
            }
        }
    }
}

// ---------------------------------------------------------------------------
// launch
// ---------------------------------------------------------------------------
extern "C" void kernel_launch(void* const* d_in, const int* in_sizes, int n_in,
                              void* d_out, int out_size) {
    const float* x    = (const float*)d_in[0];   // [1,1,8192,7168]
    const float* wgt  = (const float*)d_in[1];   // [7168,256]
    const float* bias = (const float*)d_in[2];   // [256]
    float* out = (float*)d_out;

    dim3 grid(NTOT / BN, MTOT / BM);             // (2, 64)
    gemm_kernel<<<grid, 256>>>(x, wgt);
    routing_kernel<<<MTOT, 256>>>(bias, out, out_size);
}

// round 4
// speedup vs baseline: 1.6605x; 1.6605x over previous
#include <cuda_runtime.h>
#include <cuda_bf16.h>
#include <math.h>
#include <stdint.h>

// ---------------------------------------------------------------------------
// Problem constants
// ---------------------------------------------------------------------------
#define MTOT 8192
#define NTOT 256
#define KTOT 7168

#define BM 128
#define BN 256
#define BK 32
#define NSPLIT 2
#define KSPL (KTOT / NSPLIT)     // 3584
#define NCHUNK (KSPL / BK)       // 112

#define TOPK 8

// ---------------------------------------------------------------------------
// Device scratch
// ---------------------------------------------------------------------------
__device__ float g_part[NSPLIT][(size_t)MTOT * NTOT];          // split-K partials
__device__ __nv_bfloat16 g_wt_hi[(size_t)NTOT * KTOT];         // W^T hi  [n][k]
__device__ __nv_bfloat16 g_wt_lo[(size_t)NTOT * KTOT];         // W^T lo  [n][k]

// ---------------------------------------------------------------------------
// helpers
// ---------------------------------------------------------------------------
__device__ __forceinline__ uint32_t smem_u32(const void* p) {
    uint32_t a;
    asm("{ .reg .u64 t; cvta.to.shared.u64 t, %1; cvt.u32.u64 %0, t; }" : "=r"(a) : "l"(p));
    return a;
}

#define CPA16(dst, src) \
    asm volatile("cp.async.cg.shared.global [%0], [%1], 16;" :: "r"(dst), "l"(src))
#define CPA_COMMIT() asm volatile("cp.async.commit_group;" ::: "memory")
#define CPA_WAIT0()  asm volatile("cp.async.wait_group 0;" ::: "memory")

#define LDSM4(r, addr) \
    asm volatile("ldmatrix.sync.aligned.m8n8.x4.shared.b16 {%0,%1,%2,%3}, [%4];" \
        : "=r"((r)[0]), "=r"((r)[1]), "=r"((r)[2]), "=r"((r)[3]) : "r"(addr))

#define MMA16816(c, a, b0v, b1v) \
    asm volatile("mma.sync.aligned.m16n8k16.row.col.f32.bf16.bf16.f32 " \
        "{%0,%1,%2,%3}, {%4,%5,%6,%7}, {%8,%9}, {%0,%1,%2,%3};" \
        : "+f"((c)[0]), "+f"((c)[1]), "+f"((c)[2]), "+f"((c)[3]) \
        : "r"((a)[0]), "r"((a)[1]), "r"((a)[2]), "r"((a)[3]), "r"(b0v), "r"(b1v))

// pack two floats to bf16x2 (hi parts) and return lo residuals
__device__ __forceinline__ uint32_t bf_hi_pair(float x, float y, float& lx, float& ly) {
    __nv_bfloat16 hx = __float2bfloat16(x);
    __nv_bfloat16 hy = __float2bfloat16(y);
    lx = x - __bfloat162float(hx);
    ly = y - __bfloat162float(hy);
    __nv_bfloat162 h2 = __halves2bfloat162(hx, hy);
    return *(uint32_t*)&h2;
}
__device__ __forceinline__ uint32_t bf_pair(float x, float y) {
    __nv_bfloat162 h2 = __halves2bfloat162(__float2bfloat16(x), __float2bfloat16(y));
    return *(uint32_t*)&h2;
}

// ---------------------------------------------------------------------------
// Kernel 1: W[k][n] fp32 -> Wt_hi/Wt_lo[n][k] bf16 (transpose + split)
// block (32,8), grid (8, 224)
// ---------------------------------------------------------------------------
__global__ void convert_w_kernel(const float* __restrict__ W) {
    __shared__ float tile[32][33];
    const int n0 = blockIdx.x * 32;
    const int k0 = blockIdx.y * 32;
    const int tx = threadIdx.x, ty = threadIdx.y;

#pragma unroll
    for (int i = 0; i < 4; i++)
        tile[ty + i * 8][tx] = W[(size_t)(k0 + ty + i * 8) * NTOT + n0 + tx];
    __syncthreads();
#pragma unroll
    for (int i = 0; i < 4; i++) {
        float v = tile[tx][ty + i * 8];
        __nv_bfloat16 hi = __float2bfloat16(v);
        float lo = v - __bfloat162float(hi);
        size_t o = (size_t)(n0 + ty + i * 8) * KTOT + k0 + tx;
        g_wt_hi[o] = hi;
        g_wt_lo[o] = __float2bfloat16(lo);
    }
}

// ---------------------------------------------------------------------------
// Kernel 2: bf16x3 mma.sync GEMM
// grid (NSPLIT, MTOT/BM) = (2, 64); 256 threads; 128 KB dynamic smem
//
// per-stage smem layout (stage stride 64 KB):
//   ARAW  fp32 128x32  (16 KB) @ 0       rows of 128 B
//   AHI   bf16 128x32  ( 8 KB) @ 16384   rows of 64 B, XOR-swizzled 16B chunks
//   ALO                ( 8 KB) @ 24576
//   BHI   bf16 256x32  (16 KB) @ 32768
//   BLO                (16 KB) @ 49152
// swizzle: chunk' = chunk ^ ((row>>1)&3)
// ---------------------------------------------------------------------------
#define ST(s)    ((s) * 65536)
#define ARAW_OFF 0
#define AHI_OFF  16384
#define ALO_OFF  24576
#define BHI_OFF  32768
#define BLO_OFF  49152
#define SMEM_DYN 131072

__global__ __launch_bounds__(256, 1)
void gemm_kernel(const float* __restrict__ A) {
    extern __shared__ char smem[];
    const uint32_t sbase = smem_u32(smem);

    const int tid  = threadIdx.x;
    const int lane = tid & 31;
    const int wid  = tid >> 5;
    const int wm = wid >> 2, wn = wid & 3;     // warp grid 2 x 4
    const int m0 = wm * 64, n0 = wn * 64;      // warp tile 64 x 64
    const int split = blockIdx.x;
    const int bm    = blockIdx.y * BM;
    const int kbase = split * KSPL;

    const float* Ag = A + (size_t)bm * KTOT + kbase;
    const char* whB = (const char*)g_wt_hi + ((size_t)tid * KTOT + kbase) * 2;
    const char* wlB = (const char*)g_wt_lo + ((size_t)tid * KTOT + kbase) * 2;

    // per-thread ldmatrix geometry
    const int ka = lane >> 4;            // A k-half select (0/1)
    const int kb = (lane >> 3) & 1;      // B k-half select
    int offA[4], xA[4], offB[4], xB[4];
#pragma unroll
    for (int mt = 0; mt < 4; mt++) {
        int r = m0 + mt * 16 + (lane & 15);
        offA[mt] = r * 64;  xA[mt] = (r >> 1) & 3;
    }
#pragma unroll
    for (int j = 0; j < 4; j++) {
        int n = n0 + j * 16 + (lane >> 4) * 8 + (lane & 7);
        offB[j] = n * 64;  xB[j] = (n >> 1) & 3;
    }

    // cp.async geometry: thread owns row (tid&127), chunks 4*(tid>>7)..+3 of ARAW;
    // and row tid (0..255), chunks 0..3 of BHI/BLO.
    const int arow = tid & 127;
    const int ach0 = (tid >> 7) * 4;
    const int bswz = (tid >> 1) & 3;

    float acc[4][8][4];
#pragma unroll
    for (int mt = 0; mt < 4; mt++)
#pragma unroll
        for (int nt = 0; nt < 8; nt++)
#pragma unroll
            for (int q = 0; q < 4; q++) acc[mt][nt][q] = 0.0f;

    // ---- stage loaders -----------------------------------------------------
    auto issue_loads = [&](int kt, int s) {
        const int kc = kt * BK;              // k offset within split (elements)
        uint32_t araw = sbase + ST(s) + ARAW_OFF;
        const char* asrc = (const char*)(Ag + (size_t)arow * KTOT + kc) + ach0 * 16;
#pragma unroll
        for (int i = 0; i < 4; i++)
            CPA16(araw + arow * 128 + (ach0 + i) * 16, asrc + i * 16);

        uint32_t bhi = sbase + ST(s) + BHI_OFF + tid * 64;
        uint32_t blo = sbase + ST(s) + BLO_OFF + tid * 64;
        const char* wh = whB + (size_t)kc * 2;
        const char* wl = wlB + (size_t)kc * 2;
#pragma unroll
        for (int c = 0; c < 4; c++) {
            CPA16(bhi + 16 * (c ^ bswz), wh + c * 16);
            CPA16(blo + 16 * (c ^ bswz), wl + c * 16);
        }
        CPA_COMMIT();
    };

    auto convert_A = [&](int s) {
        const char* sraw = smem + ST(s) + ARAW_OFF;
        char* shi = smem + ST(s) + AHI_OFF;
        char* slo = smem + ST(s) + ALO_OFF;
#pragma unroll
        for (int i = 0; i < 2; i++) {
            int oct = 2 * (tid >> 7) + i;                 // 8 fp32 per oct
            const float4* ar = (const float4*)(sraw + arow * 128 + oct * 32);
            float4 v0 = ar[0], v1 = ar[1];
            float l0, l1, l2, l3, l4, l5, l6, l7;
            uint4 uh, ul;
            uh.x = bf_hi_pair(v0.x, v0.y, l0, l1);
            uh.y = bf_hi_pair(v0.z, v0.w, l2, l3);
            uh.z = bf_hi_pair(v1.x, v1.y, l4, l5);
            uh.w = bf_hi_pair(v1.z, v1.w, l6, l7);
            ul.x = bf_pair(l0, l1);
            ul.y = bf_pair(l2, l3);
            ul.z = bf_pair(l4, l5);
            ul.w = bf_pair(l6, l7);
            uint32_t off = arow * 64 + 16 * (oct ^ ((arow >> 1) & 3));
            *(uint4*)(shi + off) = uh;
            *(uint4*)(slo + off) = ul;
        }
    };

    auto compute = [&](int s) {
        const uint32_t ahi = sbase + ST(s) + AHI_OFF;
        const uint32_t alo = sbase + ST(s) + ALO_OFF;
        const uint32_t bhi = sbase + ST(s) + BHI_OFF;
        const uint32_t blo = sbase + ST(s) + BLO_OFF;
#pragma unroll
        for (int ks = 0; ks < 2; ks++) {
            uint32_t aH[4][4], aX[4][4], bb[4][4];
            const int ca = (ks << 1) | ka;
            const int cb = (ks << 1) | kb;
#pragma unroll
            for (int mt = 0; mt < 4; mt++)
                LDSM4(aH[mt], ahi + offA[mt] + 16 * (ca ^ xA[mt]));
#pragma unroll
            for (int j = 0; j < 4; j++)
                LDSM4(bb[j], bhi + offB[j] + 16 * (cb ^ xB[j]));
            // hi * hi
#pragma unroll
            for (int mt = 0; mt < 4; mt++)
#pragma unroll
                for (int j = 0; j < 4; j++) {
                    MMA16816(acc[mt][2 * j],     aH[mt], bb[j][0], bb[j][1]);
                    MMA16816(acc[mt][2 * j + 1], aH[mt], bb[j][2], bb[j][3]);
                }
            // lo * hi
#pragma unroll
            for (int mt = 0; mt < 4; mt++)
                LDSM4(aX[mt], alo + offA[mt] + 16 * (ca ^ xA[mt]));
#pragma unroll
            for (int mt = 0; mt < 4; mt++)
#pragma unroll
                for (int j = 0; j < 4; j++) {
                    MMA16816(acc[mt][2 * j],     aX[mt], bb[j][0], bb[j][1]);
                    MMA16816(acc[mt][2 * j + 1], aX[mt], bb[j][2], bb[j][3]);
                }
            // hi * lo
#pragma unroll
            for (int j = 0; j < 4; j++)
                LDSM4(bb[j], blo + offB[j] + 16 * (cb ^ xB[j]));
#pragma unroll
            for (int mt = 0; mt < 4; mt++)
#pragma unroll
                for (int j = 0; j < 4; j++) {
                    MMA16816(acc[mt][2 * j],     aH[mt], bb[j][0], bb[j][1]);
                    MMA16816(acc[mt][2 * j + 1], aH[mt], bb[j][2], bb[j][3]);
                }
        }
    };

    // ---- pipeline ----------------------------------------------------------
    issue_loads(0, 0);
    CPA_WAIT0();
    convert_A(0);
    __syncthreads();

    for (int kt = 0; kt < NCHUNK; kt++) {
        const int s = kt & 1, ns = s ^ 1;
        if (kt + 1 < NCHUNK) issue_loads(kt + 1, ns);
        compute(s);
        if (kt + 1 < NCHUNK) { CPA_WAIT0(); convert_A(ns); }
        __syncthreads();
    }

    // ---- epilogue: write fp32 partials -------------------------------------
    float* gp = g_part[split];
#pragma unroll
    for (int mt = 0; mt < 4; mt++) {
        int r0 = bm + m0 + mt * 16 + (lane >> 2);
#pragma unroll
        for (int nt = 0; nt < 8; nt++) {
            int cg = n0 + nt * 8 + 2 * (lane & 3);
            float2 v0 = make_float2(acc[mt][nt][0], acc[mt][nt][1]);
            float2 v1 = make_float2(acc[mt][nt][2], acc[mt][nt][3]);
            *(float2*)(gp + (size_t)r0 * NTOT + cg)       = v0;
            *(float2*)(gp + (size_t)(r0 + 8) * NTOT + cg) = v1;
        }
    }
}

// ---------------------------------------------------------------------------
// Kernel 3: routing. one block per token, 256 threads.
// ---------------------------------------------------------------------------
__global__ __launch_bounds__(256)
void routing_kernel(const float* __restrict__ bias, float* __restrict__ out, int out_size) {
    const int b = blockIdx.x;
    const int e = threadIdx.x;
    const int w = e >> 5;
    const int lane = e & 31;

    __shared__ float sc[256];
    __shared__ float redmax[8], redsum[8];
    __shared__ float gsc[8];
    __shared__ int   gsel[8];
    __shared__ float wtv[8][8];
    __shared__ int   wti[8][8];

    float l = g_part[0][(size_t)b * NTOT + e] + g_part[1][(size_t)b * NTOT + e];

    // softmax max
    float m = l;
#pragma unroll
    for (int o = 16; o; o >>= 1) m = fmaxf(m, __shfl_xor_sync(0xFFFFFFFFu, m, o));
    if (lane == 0) redmax[w] = m;
    __syncthreads();
    if (e == 0) {
        float mm = redmax[0];
#pragma unroll
        for (int i = 1; i < 8; i++) mm = fmaxf(mm, redmax[i]);
        redmax[0] = mm;
    }
    __syncthreads();
    const float gmax = redmax[0];

    // softmax sum
    float p = expf(l - gmax);
    float s = p;
#pragma unroll
    for (int o = 16; o; o >>= 1) s += __shfl_xor_sync(0xFFFFFFFFu, s, o);
    if (lane == 0) redsum[w] = s;
    __syncthreads();
    if (e == 0) {
        float ss = redsum[0];
#pragma unroll
        for (int i = 1; i < 8; i++) ss += redsum[i];
        redsum[0] = ss;
    }
    __syncthreads();

    const float score = p / redsum[0];
    sc[e] = score;
    const float vb = score + bias[e];

    // per-group top2 (warp butterfly top-2 merge)
    float m1 = vb, m2 = -INFINITY;
#pragma unroll
    for (int o = 16; o; o >>= 1) {
        float o1 = __shfl_xor_sync(0xFFFFFFFFu, m1, o);
        float o2 = __shfl_xor_sync(0xFFFFFFFFu, m2, o);
        float r1 = fmaxf(m1, o1);
        float r2 = fmaxf(fminf(m1, o1), fmaxf(m2, o2));
        m1 = r1; m2 = r2;
    }
    if (lane == 0) gsc[w] = m1 + m2;
    __syncthreads();

    // top-4 groups (ties -> lower index)
    if (e == 0) {
#pragma unroll
        for (int i = 0; i < 8; i++) gsel[i] = 0;
        for (int t = 0; t < 4; t++) {
            float bv = -INFINITY; int bi = -1;
#pragma unroll
            for (int i = 0; i < 8; i++)
                if (!gsel[i] && gsc[i] > bv) { bv = gsc[i]; bi = i; }
            gsel[bi] = 1;
        }
    }
    __syncthreads();

    // per-warp top-8 (shfl-only; masked groups produce -inf candidates)
    float v = gsel[w] ? vb : -INFINITY;
    int idx = e;
#pragma unroll
    for (int r = 0; r < TOPK; r++) {
        float bv = v; int bi = idx;
#pragma unroll
        for (int o = 16; o; o >>= 1) {
            float ov = __shfl_xor_sync(0xFFFFFFFFu, bv, o);
            int   oi = __shfl_xor_sync(0xFFFFFFFFu, bi, o);
            if (ov > bv || (ov == bv && oi < bi)) { bv = ov; bi = oi; }
        }
        if (lane == 0) { wtv[w][r] = bv; wti[w][r] = bi; }
        if (idx == bi) v = -INFINITY;
    }
    __syncthreads();

    // warp 0 merges the 64 candidates
    if (w == 0) {
        float v0 = wtv[lane >> 3][lane & 7];
        int   i0 = wti[lane >> 3][lane & 7];
        float v1 = wtv[4 + (lane >> 3)][lane & 7];
        int   i1 = wti[4 + (lane >> 3)][lane & 7];
        int ci[TOPK];
#pragma unroll
        for (int r = 0; r < TOPK; r++) {
            float cv; int cc;
            if (v0 > v1 || (v0 == v1 && i0 < i1)) { cv = v0; cc = i0; }
            else                                  { cv = v1; cc = i1; }
#pragma unroll
            for (int o = 16; o; o >>= 1) {
                float ov = __shfl_xor_sync(0xFFFFFFFFu, cv, o);
                int   oi = __shfl_xor_sync(0xFFFFFFFFu, cc, o);
                if (ov > cv || (ov == cv && oi < cc)) { cv = ov; cc = oi; }
            }
            ci[r] = cc;
            if (i0 == cc) v0 = -INFINITY;
            if (i1 == cc) v1 = -INFINITY;
        }
        if (lane == 0) {
            float wv[TOPK], ssum = 0.0f;
#pragma unroll
            for (int r = 0; r < TOPK; r++) { wv[r] = sc[ci[r]]; ssum += wv[r]; }
#pragma unroll
            for (int r = 0; r < TOPK; r++)
                out[(size_t)b * TOPK + r] = (wv[r] / ssum + 1e-20f) * 2.5f;
            if (out_size >= 2 * MTOT * TOPK) {
                float* oidx = out + (size_t)MTOT * TOPK;
#pragma unroll
                for (int r = 0; r < TOPK; r++)
                    oidx[(size_t)b * TOPK + r] = (float)ci[r];
            }
        }
    }
}

// ---------------------------------------------------------------------------
// launch
// ---------------------------------------------------------------------------
extern "C" void kernel_launch(void* const* d_in, const int* in_sizes, int n_in,
                              void* d_out, int out_size) {
    const float* x    = (const float*)d_in[0];
    const float* wgt  = (const float*)d_in[1];
    const float* bias = (const float*)d_in[2];
    float* out = (float*)d_out;

    cudaFuncSetAttribute(gemm_kernel,
                         cudaFuncAttributeMaxDynamicSharedMemorySize, SMEM_DYN);

    convert_w_kernel<<<dim3(NTOT / 32, KTOT / 32), dim3(32, 8)>>>(wgt);
    gemm_kernel<<<dim3(NSPLIT, MTOT / BM), 256, SMEM_DYN>>>(x);
    routing_kernel<<<MTOT, 256>>>(bias, out, out_size);
}